// round 3
// baseline (speedup 1.0000x reference)
#include <cuda_runtime.h>

#define NB 8
#define S_LEN 4096
#define D 1024
#define D4 (D / 4)                       // 256 float4 per row
#define CHUNKS 64
#define ROWS_PER_CHUNK (S_LEN / CHUNKS)  // 64

// Scratch (allocation-free rule: __device__ globals)
__device__ float g_partial[NB * CHUNKS * D];  // 2 MB
__device__ float g_vsum[NB * D];
__device__ float g_tmp[NB * D];

// ---------------------------------------------------------------------------
// Stage 1: partial column-sum of V over a 64-row chunk.
// grid = (CHUNKS, NB), block = 256. Thread t owns float4 column t.
// 4 independent accumulators for ILP; loads fully independent (high MLP).
__global__ void __launch_bounds__(256) reduce_partial(const float4* __restrict__ V) {
    const int t = threadIdx.x;
    const int c = blockIdx.x;
    const int n = blockIdx.y;
    const float4* base =
        V + ((size_t)n * S_LEN + (size_t)c * ROWS_PER_CHUNK) * D4 + t;
    float4 a0 = make_float4(0.f, 0.f, 0.f, 0.f);
    float4 a1 = a0, a2 = a0, a3 = a0;
#pragma unroll 4
    for (int s = 0; s < ROWS_PER_CHUNK; s += 4) {
        float4 v0 = base[(size_t)(s + 0) * D4];
        float4 v1 = base[(size_t)(s + 1) * D4];
        float4 v2 = base[(size_t)(s + 2) * D4];
        float4 v3 = base[(size_t)(s + 3) * D4];
        a0.x += v0.x; a0.y += v0.y; a0.z += v0.z; a0.w += v0.w;
        a1.x += v1.x; a1.y += v1.y; a1.z += v1.z; a1.w += v1.w;
        a2.x += v2.x; a2.y += v2.y; a2.z += v2.z; a2.w += v2.w;
        a3.x += v3.x; a3.y += v3.y; a3.z += v3.z; a3.w += v3.w;
    }
    float4 acc;
    acc.x = (a0.x + a1.x) + (a2.x + a3.x);
    acc.y = (a0.y + a1.y) + (a2.y + a3.y);
    acc.z = (a0.z + a1.z) + (a2.z + a3.z);
    acc.w = (a0.w + a1.w) + (a2.w + a3.w);
    reinterpret_cast<float4*>(g_partial)[((size_t)n * CHUNKS + c) * D4 + t] = acc;
}

// ---------------------------------------------------------------------------
// Stage 2: fold the 64 partials. grid = NB, block = 256.
__global__ void __launch_bounds__(256) reduce_final() {
    const int t = threadIdx.x;
    const int n = blockIdx.x;
    const float4* p =
        reinterpret_cast<const float4*>(g_partial) + (size_t)n * CHUNKS * D4 + t;
    float4 a0 = make_float4(0.f, 0.f, 0.f, 0.f);
    float4 a1 = a0;
#pragma unroll 8
    for (int c = 0; c < CHUNKS; c += 2) {
        float4 v0 = p[(size_t)(c + 0) * D4];
        float4 v1 = p[(size_t)(c + 1) * D4];
        a0.x += v0.x; a0.y += v0.y; a0.z += v0.z; a0.w += v0.w;
        a1.x += v1.x; a1.y += v1.y; a1.z += v1.z; a1.w += v1.w;
    }
    float4 acc;
    acc.x = a0.x + a1.x; acc.y = a0.y + a1.y;
    acc.z = a0.z + a1.z; acc.w = a0.w + a1.w;
    reinterpret_cast<float4*>(g_vsum)[n * D4 + t] = acc;
}

// ---------------------------------------------------------------------------
// Tiled batch-8 GEMV: out[n][j] = dot(x[n,:], W[j,:]) + bias_scale * b[j]
// grid = 64 blocks (16 j each), block = 256 (8 warps, 2 j per warp).
// x staged in smem ONCE per block; W read exactly once, coalesced.
#define JPB 16  // j per block
#define JPW 2   // j per warp
__global__ void __launch_bounds__(256) gemv8(const float4* __restrict__ W,
                                             const float* __restrict__ b,
                                             float bias_scale, int stage,
                                             float* __restrict__ dout) {
    __shared__ float4 xs[NB * D4];   // 32 KB
    __shared__ float  sout[JPB * NB];

    const int t = threadIdx.x;
    const int lane = t & 31;
    const int wid = t >> 5;

    const float4* xin = reinterpret_cast<const float4*>(stage == 0 ? g_vsum : g_tmp);
    float* out = (stage == 0) ? g_tmp : dout;

    // Stage x into smem: 2048 float4, 256 threads -> 8 each, coalesced.
#pragma unroll 8
    for (int i = t; i < NB * D4; i += 256) xs[i] = xin[i];
    __syncthreads();

    const int j0 = blockIdx.x * JPB + wid * JPW;  // warp owns j0, j0+1

    float acc[JPW][NB];
#pragma unroll
    for (int jj = 0; jj < JPW; ++jj)
#pragma unroll
        for (int n = 0; n < NB; ++n) acc[jj][n] = 0.f;

    const float4* w0p = W + (size_t)(j0 + 0) * D4 + lane;
    const float4* w1p = W + (size_t)(j0 + 1) * D4 + lane;

#pragma unroll
    for (int i = 0; i < D4 / 32; ++i) {  // 8 chunks of 32 float4
        float4 w0 = w0p[i * 32];
        float4 w1 = w1p[i * 32];
#pragma unroll
        for (int n = 0; n < NB; ++n) {
            float4 x = xs[n * D4 + i * 32 + lane];
            acc[0][n] += w0.x * x.x + w0.y * x.y + w0.z * x.z + w0.w * x.w;
            acc[1][n] += w1.x * x.x + w1.y * x.y + w1.z * x.z + w1.w * x.w;
        }
    }

    // 16 independent warp reductions (ILP hides SHFL latency).
#pragma unroll
    for (int jj = 0; jj < JPW; ++jj)
#pragma unroll
        for (int n = 0; n < NB; ++n) {
#pragma unroll
            for (int ofs = 16; ofs > 0; ofs >>= 1)
                acc[jj][n] += __shfl_xor_sync(0xFFFFFFFFu, acc[jj][n], ofs);
        }

    if (lane == 0) {
#pragma unroll
        for (int jj = 0; jj < JPW; ++jj)
#pragma unroll
            for (int n = 0; n < NB; ++n)
                sout[(wid * JPW + jj) * NB + n] = acc[jj][n];
    }
    __syncthreads();

    // 128 outputs per block (16 j x 8 n); thread t < 128 writes one.
    if (t < JPB * NB) {
        const int jl = t / NB;
        const int n  = t % NB;
        const int j  = blockIdx.x * JPB + jl;
        out[n * D + j] = sout[jl * NB + n] + bias_scale * b[j];
    }
}

// ---------------------------------------------------------------------------
extern "C" void kernel_launch(void* const* d_in, const int* in_sizes, int n_in,
                              void* d_out, int out_size) {
    (void)in_sizes; (void)n_in; (void)out_size;
    // metadata order: Q(0) K(1) V(2) Wq(3) bq(4) Wk(5) bk(6) Wv(7) bv(8) Wo(9) bo(10)
    // softmax over a size-1 axis == 1.0 -> Q, K, Wq, bq, Wk, bk are dead inputs.
    const float4* V  = (const float4*)d_in[2];
    const float4* Wv = (const float4*)d_in[7];
    const float*  bv = (const float*)d_in[8];
    const float4* Wo = (const float4*)d_in[9];
    const float*  bo = (const float*)d_in[10];
    float* out = (float*)d_out;

    reduce_partial<<<dim3(CHUNKS, NB), 256>>>(V);
    reduce_final<<<NB, 256>>>();
    gemv8<<<D / JPB, 256>>>(Wv, bv, (float)S_LEN, 0, nullptr);
    gemv8<<<D / JPB, 256>>>(Wo, bo, 1.0f, 1, out);
}

// round 6
// speedup vs baseline: 1.2775x; 1.2775x over previous
#include <cuda_runtime.h>

#define NB 8
#define S_LEN 4096
#define D 1024
#define D4 (D / 4)                       // 256 float4 per row
#define CHUNKS 64
#define ROWS_PER_CHUNK (S_LEN / CHUNKS)  // 64

// Scratch (allocation-free rule: __device__ globals)
__device__ float g_partial[NB * CHUNKS * D];  // 2 MB
__device__ float g_vsum[NB * D];
__device__ float g_tmp[NB * D];

// ---------------------------------------------------------------------------
// Stage 1: partial column-sum of V over a 64-row chunk.
// grid = (CHUNKS, NB) = 512 blocks, block = 256. Thread t owns float4 col t.
__global__ void __launch_bounds__(256) reduce_partial(const float4* __restrict__ V) {
    const int t = threadIdx.x;
    const int c = blockIdx.x;
    const int n = blockIdx.y;
    const float4* base =
        V + ((size_t)n * S_LEN + (size_t)c * ROWS_PER_CHUNK) * D4 + t;
    float4 a0 = make_float4(0.f, 0.f, 0.f, 0.f);
    float4 a1 = a0, a2 = a0, a3 = a0;
#pragma unroll 4
    for (int s = 0; s < ROWS_PER_CHUNK; s += 4) {
        float4 v0 = base[(size_t)(s + 0) * D4];
        float4 v1 = base[(size_t)(s + 1) * D4];
        float4 v2 = base[(size_t)(s + 2) * D4];
        float4 v3 = base[(size_t)(s + 3) * D4];
        a0.x += v0.x; a0.y += v0.y; a0.z += v0.z; a0.w += v0.w;
        a1.x += v1.x; a1.y += v1.y; a1.z += v1.z; a1.w += v1.w;
        a2.x += v2.x; a2.y += v2.y; a2.z += v2.z; a2.w += v2.w;
        a3.x += v3.x; a3.y += v3.y; a3.z += v3.z; a3.w += v3.w;
    }
    float4 acc;
    acc.x = (a0.x + a1.x) + (a2.x + a3.x);
    acc.y = (a0.y + a1.y) + (a2.y + a3.y);
    acc.z = (a0.z + a1.z) + (a2.z + a3.z);
    acc.w = (a0.w + a1.w) + (a2.w + a3.w);
    reinterpret_cast<float4*>(g_partial)[((size_t)n * CHUNKS + c) * D4 + t] = acc;
}

// ---------------------------------------------------------------------------
// Stage 2: fold the 64 partials, parallel over columns.
// grid = NB * 8 = 64 blocks, block = 256 (8 k-slices x 32 cols).
__global__ void __launch_bounds__(256) reduce_final() {
    __shared__ float4 sred[8][32];
    const int t = threadIdx.x;
    const int lane = t & 31;
    const int slice = t >> 5;                 // 0..7, each sums 8 chunks
    const int n  = blockIdx.x >> 3;
    const int cg = blockIdx.x & 7;            // column group (32 float4)
    const int col = cg * 32 + lane;

    const float4* p =
        reinterpret_cast<const float4*>(g_partial) + (size_t)n * CHUNKS * D4 + col;
    float4 a = make_float4(0.f, 0.f, 0.f, 0.f);
#pragma unroll
    for (int c = 0; c < 8; ++c) {
        float4 v = p[(size_t)(slice * 8 + c) * D4];
        a.x += v.x; a.y += v.y; a.z += v.z; a.w += v.w;
    }
    sred[slice][lane] = a;
    __syncthreads();
    if (slice == 0) {
        float4 s = sred[0][lane];
#pragma unroll
        for (int k = 1; k < 8; ++k) {
            float4 v = sred[k][lane];
            s.x += v.x; s.y += v.y; s.z += v.z; s.w += v.w;
        }
        reinterpret_cast<float4*>(g_vsum)[n * D4 + col] = s;
    }
}

// ---------------------------------------------------------------------------
// Tiled batch-8 GEMV: out[n][j] = dot(x[n,:], W[j,:]) + bias_scale * b[j]
// grid = 128 blocks (8 j each), block = 128 (4 warps, 2 j per warp).
// Each lane issues 16 independent W float4 loads (whole W slice in flight).
#define JPB 8   // j per block
#define JPW 2   // j per warp
__global__ void __launch_bounds__(128) gemv8(const float4* __restrict__ W,
                                             const float* __restrict__ b,
                                             float bias_scale, int stage,
                                             float* __restrict__ dout) {
    __shared__ float4 xs[NB * D4];   // 32 KB
    __shared__ float  sout[JPB * NB];

    const int t = threadIdx.x;
    const int lane = t & 31;
    const int wid = t >> 5;          // 0..3

    const float4* xin = reinterpret_cast<const float4*>(stage == 0 ? g_vsum : g_tmp);
    float* out = (stage == 0) ? g_tmp : dout;

    // Stage x into smem: 2048 float4, 128 threads -> 16 each, coalesced.
#pragma unroll 16
    for (int i = t; i < NB * D4; i += 128) xs[i] = xin[i];
    __syncthreads();

    const int j0 = blockIdx.x * JPB + wid * JPW;  // warp owns j0, j0+1

    const float4* w0p = W + (size_t)(j0 + 0) * D4 + lane;
    const float4* w1p = W + (size_t)(j0 + 1) * D4 + lane;

    float acc[JPW][NB];
#pragma unroll
    for (int jj = 0; jj < JPW; ++jj)
#pragma unroll
        for (int n = 0; n < NB; ++n) acc[jj][n] = 0.f;

#pragma unroll
    for (int i = 0; i < D4 / 32; ++i) {  // 8 chunks of 32 float4; loads hoist
        float4 w0 = w0p[i * 32];
        float4 w1 = w1p[i * 32];
#pragma unroll
        for (int n = 0; n < NB; ++n) {
            float4 x = xs[n * D4 + i * 32 + lane];
            acc[0][n] += w0.x * x.x + w0.y * x.y + w0.z * x.z + w0.w * x.w;
            acc[1][n] += w1.x * x.x + w1.y * x.y + w1.z * x.z + w1.w * x.w;
        }
    }

    // 16 independent warp reductions (ILP hides SHFL latency).
#pragma unroll
    for (int jj = 0; jj < JPW; ++jj)
#pragma unroll
        for (int n = 0; n < NB; ++n) {
#pragma unroll
            for (int ofs = 16; ofs > 0; ofs >>= 1)
                acc[jj][n] += __shfl_xor_sync(0xFFFFFFFFu, acc[jj][n], ofs);
        }

    if (lane == 0) {
#pragma unroll
        for (int jj = 0; jj < JPW; ++jj)
#pragma unroll
            for (int n = 0; n < NB; ++n)
                sout[(wid * JPW + jj) * NB + n] = acc[jj][n];
    }
    __syncthreads();

    // 64 outputs per block (8 j x 8 n); thread t < 64 writes one.
    if (t < JPB * NB) {
        const int jl = t / NB;
        const int n  = t % NB;
        const int j  = blockIdx.x * JPB + jl;
        out[n * D + j] = sout[jl * NB + n] + bias_scale * b[j];
    }
}

// ---------------------------------------------------------------------------
extern "C" void kernel_launch(void* const* d_in, const int* in_sizes, int n_in,
                              void* d_out, int out_size) {
    (void)in_sizes; (void)n_in; (void)out_size;
    // metadata order: Q(0) K(1) V(2) Wq(3) bq(4) Wk(5) bk(6) Wv(7) bv(8) Wo(9) bo(10)
    // softmax over a size-1 axis == 1.0 -> Q, K, Wq, bq, Wk, bk are dead inputs.
    const float4* V  = (const float4*)d_in[2];
    const float4* Wv = (const float4*)d_in[7];
    const float*  bv = (const float*)d_in[8];
    const float4* Wo = (const float4*)d_in[9];
    const float*  bo = (const float*)d_in[10];
    float* out = (float*)d_out;

    reduce_partial<<<dim3(CHUNKS, NB), 256>>>(V);
    reduce_final<<<NB * 8, 256>>>();
    gemv8<<<D / JPB, 128>>>(Wv, bv, (float)S_LEN, 0, nullptr);
    gemv8<<<D / JPB, 128>>>(Wo, bo, 1.0f, 1, out);
}